// round 10
// baseline (speedup 1.0000x reference)
#include <cuda_runtime.h>
#include <cuda_bf16.h>
#include <cstdint>

#define M_DIM 4096
#define K_DIM 4096
#define N_DIM 11008
#define KW    (K_DIM / 2)       // packed int32 per weight row = 2048

#define BM 128
#define BN 128
#define BK 64                   // K-elems per tile iteration
#define K_ITERS (K_DIM / BK)    // 64
#define THREADS 256

// smem: A double 2x16KB, B double 2x16KB, z 512B
#define SM_A(s)   ((s) * (BM * 128))
#define SM_B(s)   (2 * BM * 128 + (s) * (BN * 128))
#define SM_Z      (4 * BM * 128)
#define SMEM_BYTES (SM_Z + BN * 4)

#define SWZ(off) ((off) ^ (((off) >> 3) & 0x70))

// ---------------- device scratch (32 MB) -----------------------------------
__device__ __nv_bfloat16 g_qa[(size_t)M_DIM * K_DIM];   // quantized activations, integer-valued bf16

__device__ __forceinline__ uint32_t smem_u32(const void* p) {
    uint32_t a;
    asm("{ .reg .u64 t; cvta.to.shared.u64 t, %1; cvt.u32.u64 %0, t; }" : "=r"(a) : "l"(p));
    return a;
}

// ---------------- kernel 1: static fake-quant x -> bf16 (integer values) ---
__global__ void quant_kernel(const float* __restrict__ x,
                             const float* __restrict__ clampv) {
    const float cv  = clampv[0];
    const float inv = 127.0f / cv;
    size_t i = (size_t)blockIdx.x * blockDim.x + threadIdx.x;   // over M*K/4
    float4 v = reinterpret_cast<const float4*>(x)[i];
    int a = max(-127, min(127, __float2int_rn(fminf(fmaxf(v.x, -cv), cv) * inv)));
    int b = max(-127, min(127, __float2int_rn(fminf(fmaxf(v.y, -cv), cv) * inv)));
    int c = max(-127, min(127, __float2int_rn(fminf(fmaxf(v.z, -cv), cv) * inv)));
    int d = max(-127, min(127, __float2int_rn(fminf(fmaxf(v.w, -cv), cv) * inv)));
    __nv_bfloat162 p0 = make_bfloat162(__float2bfloat16((float)a), __float2bfloat16((float)b));
    __nv_bfloat162 p1 = make_bfloat162(__float2bfloat16((float)c), __float2bfloat16((float)d));
    reinterpret_cast<uint2*>(g_qa)[i] = make_uint2(*(uint32_t*)&p0, *(uint32_t*)&p1);
}

// ---------------- kernel 2: fused bf16 GEMM, in-kernel W4 magic convert ----
__global__ __launch_bounds__(THREADS, 2)
void gemm_kernel(const int* __restrict__ qw,
                 const int* __restrict__ qz,
                 const float* __restrict__ sc,
                 const float* __restrict__ bias,
                 const float* __restrict__ clampv,
                 float* __restrict__ C) {
    extern __shared__ char smem[];
    const uint32_t sbase = smem_u32(smem);
    const int tid  = threadIdx.x;
    const int wid  = tid >> 5;
    const int lane = tid & 31;
    const int m0 = blockIdx.y * BM;
    const int n0 = blockIdx.x * BN;
    const int warp_m = (wid & 3) * 32;
    const int warp_n = (wid >> 2) * 64;

    if (tid < BN)
        *reinterpret_cast<int*>(smem + SM_Z + tid * 4) = qz[n0 + tid];

    float acc[2][8][4];
#pragma unroll
    for (int f = 0; f < 2; f++)
#pragma unroll
        for (int j = 0; j < 8; j++)
#pragma unroll
            for (int q = 0; q < 4; q++) acc[f][j][q] = 0.0f;

    const __nv_bfloat16* gA = g_qa + (size_t)m0 * K_DIM;

    // A-load (cp.async): 1024 x 16B chunks, 4/thread
    const int ld_row = tid >> 3;
    const int ld_seg = tid & 7;

#define LOAD_A(s, k0)                                                            \
    do {                                                                         \
        uint32_t sA_ = sbase + SM_A(s);                                          \
        _Pragma("unroll")                                                        \
        for (int t = 0; t < 4; t++) {                                            \
            int row = ld_row + t * 32;                                           \
            uint32_t off = SWZ((uint32_t)(row * 128 + ld_seg * 16));             \
            const __nv_bfloat16* ga = gA + (size_t)row * K_DIM + (k0) + ld_seg * 8; \
            asm volatile("cp.async.cg.shared.global [%0], [%1], 16;"             \
                         :: "r"(sA_ + off), "l"(ga) : "memory");                 \
        }                                                                        \
        asm volatile("cp.async.commit_group;" ::: "memory");                     \
    } while (0)

    // B geometry: row = tid>>1 (0..127), half = tid&1 -> 32 k-elems = 16 int32
    const int b_row  = tid >> 1;
    const int b_half = tid & 1;
    const int* gW = qw + (size_t)(n0 + b_row) * KW + b_half * 16;

    int4 bwreg[4];
#pragma unroll
    for (int q = 0; q < 4; q++)
        bwreg[q] = reinterpret_cast<const int4*>(gW)[q];

    LOAD_A(0, 0);
    __syncthreads();   // z visible
    // zz2: bf16x2 of (128 + z) replicated (exact: ulp(128)=1)
    const int zint = *reinterpret_cast<const int*>(smem + SM_Z + b_row * 4);
    const uint32_t zhalf = 0x4300u | (uint32_t)zint;
    const uint32_t zz2 = zhalf | (zhalf << 16);

#pragma unroll 1
    for (int it = 0; it < K_ITERS; it++) {
        const int s = it & 1;

        if (it + 1 < K_ITERS) LOAD_A(s ^ 1, (it + 1) * BK);

        // ---- convert prefetched packed B -> bf16 smem (magic 0x4300) ----
        {
            char* sB = smem + SM_B(s);
#pragma unroll
            for (int q = 0; q < 4; q++) {
                int v[4] = {bwreg[q].x, bwreg[q].y, bwreg[q].z, bwreg[q].w};
                uint32_t o[4];
#pragma unroll
                for (int t = 0; t < 4; t++) {
                    // word = bf16(128+hi) | bf16(128+lo)<<16, minus (128+z) pair
                    uint32_t w = (((uint32_t)v[t] >> 4) & 0xFu)
                               | (((uint32_t)v[t] & 0xFu) << 16)
                               | 0x43004300u;
                    uint32_t r;
                    asm("sub.rn.bf16x2 %0, %1, %2;" : "=r"(r) : "r"(w), "r"(zz2));
                    o[t] = r;
                }
                uint32_t off = SWZ((uint32_t)(b_row * 128 + b_half * 64 + q * 16));
                *reinterpret_cast<uint4*>(sB + off) = *reinterpret_cast<uint4*>(o);
            }
        }

        // prefetch next packed B
        if (it + 1 < K_ITERS) {
            const int* gWn = gW + (it + 1) * (BK / 2);
#pragma unroll
            for (int q = 0; q < 4; q++)
                bwreg[q] = reinterpret_cast<const int4*>(gWn)[q];
        }

        if (it + 1 < K_ITERS) {
            asm volatile("cp.async.wait_group 1;" ::: "memory");
        } else {
            asm volatile("cp.async.wait_group 0;" ::: "memory");
        }
        __syncthreads();

        const uint32_t sA = sbase + SM_A(s);
        const uint32_t sB = sbase + SM_B(s);

#pragma unroll
        for (int ks = 0; ks < 4; ks++) {
            uint32_t a[2][4];
#pragma unroll
            for (int f = 0; f < 2; f++) {
                uint32_t off = (uint32_t)((warp_m + f * 16 + (lane & 15)) * 128
                                          + ks * 32 + (lane >> 4) * 16);
                asm volatile("ldmatrix.sync.aligned.m8n8.x4.shared.b16 {%0,%1,%2,%3}, [%4];"
                             : "=r"(a[f][0]), "=r"(a[f][1]), "=r"(a[f][2]), "=r"(a[f][3])
                             : "r"(sA + SWZ(off)));
            }
            uint32_t b[4][4];
#pragma unroll
            for (int p = 0; p < 4; p++) {
                uint32_t off = (uint32_t)((warp_n + p * 16 + (lane & 15)) * 128
                                          + ks * 32 + (lane >> 4) * 16);
                asm volatile("ldmatrix.sync.aligned.m8n8.x4.shared.b16 {%0,%1,%2,%3}, [%4];"
                             : "=r"(b[p][0]), "=r"(b[p][1]), "=r"(b[p][2]), "=r"(b[p][3])
                             : "r"(sB + SWZ(off)));
            }
#pragma unroll
            for (int f = 0; f < 2; f++)
#pragma unroll
                for (int j = 0; j < 8; j++) {
                    asm volatile(
                        "mma.sync.aligned.m16n8k16.row.col.f32.bf16.bf16.f32 "
                        "{%0,%1,%2,%3}, {%4,%5,%6,%7}, {%8,%9}, {%0,%1,%2,%3};"
                        : "+f"(acc[f][j][0]), "+f"(acc[f][j][1]),
                          "+f"(acc[f][j][2]), "+f"(acc[f][j][3])
                        : "r"(a[f][0]), "r"(a[f][1]), "r"(a[f][2]), "r"(a[f][3]),
                          "r"(b[j >> 1][j & 1]), "r"(b[j >> 1][(j & 1) + 2]));
                }
        }
        __syncthreads();
    }

    // ---- epilogue ----
    const float ascale = clampv[0] * (1.0f / 127.0f);
#pragma unroll
    for (int f = 0; f < 2; f++) {
        int r0 = m0 + warp_m + f * 16 + (lane >> 2);
#pragma unroll
        for (int j = 0; j < 8; j++) {
            int col = n0 + warp_n + j * 8 + (lane & 3) * 2;
            float2 s2 = *reinterpret_cast<const float2*>(sc + col);
            float2 b2 = *reinterpret_cast<const float2*>(bias + col);
            float s0 = ascale * s2.x, s1 = ascale * s2.y;
            float2 o0, o1;
            o0.x = s0 * acc[f][j][0] + b2.x;
            o0.y = s1 * acc[f][j][1] + b2.y;
            o1.x = s0 * acc[f][j][2] + b2.x;
            o1.y = s1 * acc[f][j][3] + b2.y;
            *reinterpret_cast<float2*>(C + (size_t)r0 * N_DIM + col) = o0;
            *reinterpret_cast<float2*>(C + (size_t)(r0 + 8) * N_DIM + col) = o1;
        }
    }
}

// ---------------- launch ---------------------------------------------------
extern "C" void kernel_launch(void* const* d_in, const int* in_sizes, int n_in,
                              void* d_out, int out_size) {
    const float* x      = (const float*)d_in[0];
    const int*   qw     = (const int*)d_in[1];
    const int*   qz     = (const int*)d_in[2];
    const float* sc     = (const float*)d_in[3];
    const float* bias   = (const float*)d_in[4];
    const float* clampv = (const float*)d_in[5];
    float* out = (float*)d_out;

    cudaFuncSetAttribute(gemm_kernel, cudaFuncAttributeMaxDynamicSharedMemorySize, SMEM_BYTES);

    quant_kernel<<<(M_DIM * (K_DIM / 4)) / 256, 256>>>(x, clampv);

    dim3 grid(N_DIM / BN, M_DIM / BM);
    gemm_kernel<<<grid, THREADS, SMEM_BYTES>>>(qw, qz, sc, bias, clampv, out);
}

// round 11
// speedup vs baseline: 1.3013x; 1.3013x over previous
#include <cuda_runtime.h>
#include <cuda_fp16.h>
#include <cstdint>

#define M_DIM 4096
#define K_DIM 4096
#define N_DIM 11008
#define KW    (K_DIM / 2)       // packed int32 per weight row

#define BM 128
#define BN 128
#define BK 64                   // K-elems per tile iteration
#define K_ITERS (K_DIM / BK)    // 64
#define THREADS 256

// smem: A double 2x16KB, B double 2x16KB
#define SM_A(s)   ((s) * (BM * 128))
#define SM_B(s)   (2 * BM * 128 + (s) * (BN * 128))
#define SMEM_BYTES (4 * BM * 128)

#define SWZ(off) ((off) ^ (((off) >> 3) & 0x70))

// ---------------- device scratch (16 MB) -----------------------------------
__device__ uint8_t g_qx[(size_t)M_DIM * K_DIM];   // biased activations: qi + 128

__device__ __forceinline__ uint32_t smem_u32(const void* p) {
    uint32_t a;
    asm("{ .reg .u64 t; cvta.to.shared.u64 t, %1; cvt.u32.u64 %0, t; }" : "=r"(a) : "l"(p));
    return a;
}
__device__ __forceinline__ uint32_t hsub2(uint32_t a, uint32_t b) {
    uint32_t r;
    asm("sub.rn.f16x2 %0, %1, %2;" : "=r"(r) : "r"(a), "r"(b));
    return r;
}

// ---------------- kernel 1: static fake-quant x -> biased u8 ---------------
__global__ void quant_kernel(const float* __restrict__ x,
                             const float* __restrict__ clampv) {
    const float cv  = clampv[0];
    const float inv = 127.0f / cv;
    size_t i = (size_t)blockIdx.x * blockDim.x + threadIdx.x;   // over M*K/4
    float4 v = reinterpret_cast<const float4*>(x)[i];
    uint32_t a = (uint32_t)(max(-127, min(127, __float2int_rn(fminf(fmaxf(v.x, -cv), cv) * inv))) + 128);
    uint32_t b = (uint32_t)(max(-127, min(127, __float2int_rn(fminf(fmaxf(v.y, -cv), cv) * inv))) + 128);
    uint32_t c = (uint32_t)(max(-127, min(127, __float2int_rn(fminf(fmaxf(v.z, -cv), cv) * inv))) + 128);
    uint32_t d = (uint32_t)(max(-127, min(127, __float2int_rn(fminf(fmaxf(v.w, -cv), cv) * inv))) + 128);
    reinterpret_cast<uint32_t*>(g_qx)[i] = a | (b << 8) | (c << 16) | (d << 24);
}

// ---------------- kernel 2: fused fp16 GEMM, magic converts ----------------
__global__ __launch_bounds__(THREADS, 2)
void gemm_kernel(const int* __restrict__ qw,
                 const int* __restrict__ qz,
                 const float* __restrict__ sc,
                 const float* __restrict__ bias,
                 const float* __restrict__ clampv,
                 float* __restrict__ C) {
    extern __shared__ char smem[];
    const uint32_t sbase = smem_u32(smem);
    const int tid  = threadIdx.x;
    const int wid  = tid >> 5;
    const int lane = tid & 31;
    const int m0 = blockIdx.y * BM;
    const int n0 = blockIdx.x * BN;
    const int warp_m = (wid & 3) * 32;
    const int warp_n = (wid >> 2) * 64;

    float acc[2][8][4];
#pragma unroll
    for (int f = 0; f < 2; f++)
#pragma unroll
        for (int j = 0; j < 8; j++)
#pragma unroll
            for (int q = 0; q < 4; q++) acc[f][j][q] = 0.0f;

    // A geometry: u8 tile 128 x 64B = 512 x 16B chunks, 2/thread
    const int a_row = tid >> 2;          // 0..63 (+64 for 2nd chunk)
    const int a_seg = tid & 3;           // 16B segment within 64B row-slice
    const uint8_t* gA0 = g_qx + (size_t)(m0 + a_row)      * K_DIM + a_seg * 16;
    const uint8_t* gA1 = g_qx + (size_t)(m0 + a_row + 64) * K_DIM + a_seg * 16;

    // B geometry: packed int4; row = tid>>1, half = tid&1 (32 k-elems = 16 int32)
    const int b_row  = tid >> 1;
    const int b_half = tid & 1;
    const int* gW = qw + (size_t)(n0 + b_row) * KW + b_half * 16;

    // fp16x2 of (1024 + z) replicated (z in [0,15], exact)
    const uint32_t zhalf = 0x6400u | (uint32_t)qz[n0 + b_row];
    const uint32_t zz2 = zhalf | (zhalf << 16);

    // prefetch iter 0
    int4 awreg[2], bwreg[4];
    awreg[0] = *reinterpret_cast<const int4*>(gA0);
    awreg[1] = *reinterpret_cast<const int4*>(gA1);
#pragma unroll
    for (int q = 0; q < 4; q++)
        bwreg[q] = reinterpret_cast<const int4*>(gW)[q];

#pragma unroll 1
    for (int it = 0; it < K_ITERS; it++) {
        const int s = it & 1;
        char* smA = smem + SM_A(s);
        char* smB = smem + SM_B(s);

        // ---- A magic convert: u8 -> fp16 (value - 1152 = qi) ----
#pragma unroll
        for (int h = 0; h < 2; h++) {
            const int v[4] = {awreg[h].x, awreg[h].y, awreg[h].z, awreg[h].w};
            uint32_t o[8];
#pragma unroll
            for (int t = 0; t < 4; t++) {
                uint32_t w01 = __byte_perm((uint32_t)v[t], 0u, 0x4140) | 0x64006400u;
                uint32_t w23 = __byte_perm((uint32_t)v[t], 0u, 0x4342) | 0x64006400u;
                o[2*t]   = hsub2(w01, 0x64806480u);   // fp16(1152) pair
                o[2*t+1] = hsub2(w23, 0x64806480u);
            }
            uint32_t off = (uint32_t)((a_row + h * 64) * 128 + a_seg * 32);
            *reinterpret_cast<uint4*>(smA + SWZ(off))      = *reinterpret_cast<uint4*>(&o[0]);
            *reinterpret_cast<uint4*>(smA + SWZ(off + 16)) = *reinterpret_cast<uint4*>(&o[4]);
        }

        // ---- B magic convert: nibbles -> fp16 (n - z) ----
#pragma unroll
        for (int q = 0; q < 4; q++) {
            const int v[4] = {bwreg[q].x, bwreg[q].y, bwreg[q].z, bwreg[q].w};
            uint32_t o[4];
#pragma unroll
            for (int t = 0; t < 4; t++) {
                uint32_t w = (((uint32_t)v[t] >> 4) & 0xFu)
                           | (((uint32_t)v[t] & 0xFu) << 16)
                           | 0x64006400u;
                o[t] = hsub2(w, zz2);
            }
            uint32_t off = SWZ((uint32_t)(b_row * 128 + b_half * 64 + q * 16));
            *reinterpret_cast<uint4*>(smB + off) = *reinterpret_cast<uint4*>(o);
        }

        // ---- prefetch next iter (latency hides under MMA) ----
        if (it + 1 < K_ITERS) {
            const int knext = (it + 1) * BK;
            awreg[0] = *reinterpret_cast<const int4*>(gA0 + knext);
            awreg[1] = *reinterpret_cast<const int4*>(gA1 + knext);
            const int* gWn = gW + (it + 1) * (BK / 2);
#pragma unroll
            for (int q = 0; q < 4; q++)
                bwreg[q] = reinterpret_cast<const int4*>(gWn)[q];
        }

        __syncthreads();   // single barrier per iteration (double-buffered)

        const uint32_t sA = sbase + SM_A(s);
        const uint32_t sB = sbase + SM_B(s);

#pragma unroll
        for (int ks = 0; ks < 4; ks++) {
            uint32_t a[2][4];
#pragma unroll
            for (int f = 0; f < 2; f++) {
                uint32_t off = (uint32_t)((warp_m + f * 16 + (lane & 15)) * 128
                                          + ks * 32 + (lane >> 4) * 16);
                asm volatile("ldmatrix.sync.aligned.m8n8.x4.shared.b16 {%0,%1,%2,%3}, [%4];"
                             : "=r"(a[f][0]), "=r"(a[f][1]), "=r"(a[f][2]), "=r"(a[f][3])
                             : "r"(sA + SWZ(off)));
            }
            uint32_t b[4][4];
#pragma unroll
            for (int p = 0; p < 4; p++) {
                uint32_t off = (uint32_t)((warp_n + p * 16 + (lane & 15)) * 128
                                          + ks * 32 + (lane >> 4) * 16);
                asm volatile("ldmatrix.sync.aligned.m8n8.x4.shared.b16 {%0,%1,%2,%3}, [%4];"
                             : "=r"(b[p][0]), "=r"(b[p][1]), "=r"(b[p][2]), "=r"(b[p][3])
                             : "r"(sB + SWZ(off)));
            }
#pragma unroll
            for (int f = 0; f < 2; f++)
#pragma unroll
                for (int j = 0; j < 8; j++) {
                    asm volatile(
                        "mma.sync.aligned.m16n8k16.row.col.f32.f16.f16.f32 "
                        "{%0,%1,%2,%3}, {%4,%5,%6,%7}, {%8,%9}, {%0,%1,%2,%3};"
                        : "+f"(acc[f][j][0]), "+f"(acc[f][j][1]),
                          "+f"(acc[f][j][2]), "+f"(acc[f][j][3])
                        : "r"(a[f][0]), "r"(a[f][1]), "r"(a[f][2]), "r"(a[f][3]),
                          "r"(b[j >> 1][j & 1]), "r"(b[j >> 1][(j & 1) + 2]));
                }
        }
    }

    // ---- epilogue: out = ascale*scale[n]*acc + bias[n] ----
    const float ascale = clampv[0] * (1.0f / 127.0f);
#pragma unroll
    for (int f = 0; f < 2; f++) {
        int r0 = m0 + warp_m + f * 16 + (lane >> 2);
#pragma unroll
        for (int j = 0; j < 8; j++) {
            int col = n0 + warp_n + j * 8 + (lane & 3) * 2;
            float2 s2 = *reinterpret_cast<const float2*>(sc + col);
            float2 b2 = *reinterpret_cast<const float2*>(bias + col);
            float s0 = ascale * s2.x, s1 = ascale * s2.y;
            float2 o0, o1;
            o0.x = s0 * acc[f][j][0] + b2.x;
            o0.y = s1 * acc[f][j][1] + b2.y;
            o1.x = s0 * acc[f][j][2] + b2.x;
            o1.y = s1 * acc[f][j][3] + b2.y;
            *reinterpret_cast<float2*>(C + (size_t)r0 * N_DIM + col) = o0;
            *reinterpret_cast<float2*>(C + (size_t)(r0 + 8) * N_DIM + col) = o1;
        }
    }
}

// ---------------- launch ---------------------------------------------------
extern "C" void kernel_launch(void* const* d_in, const int* in_sizes, int n_in,
                              void* d_out, int out_size) {
    const float* x      = (const float*)d_in[0];
    const int*   qw     = (const int*)d_in[1];
    const int*   qz     = (const int*)d_in[2];
    const float* sc     = (const float*)d_in[3];
    const float* bias   = (const float*)d_in[4];
    const float* clampv = (const float*)d_in[5];
    float* out = (float*)d_out;

    cudaFuncSetAttribute(gemm_kernel, cudaFuncAttributeMaxDynamicSharedMemorySize, SMEM_BYTES);

    quant_kernel<<<(M_DIM * (K_DIM / 4)) / 256, 256>>>(x, clampv);

    dim3 grid(N_DIM / BN, M_DIM / BM);
    gemm_kernel<<<grid, THREADS, SMEM_BYTES>>>(qw, qz, sc, bias, clampv, out);
}

// round 14
// speedup vs baseline: 1.5442x; 1.1867x over previous
#include <cuda_runtime.h>
#include <cuda_fp16.h>
#include <cstdint>

#define M_DIM 4096
#define K_DIM 4096
#define N_DIM 11008
#define KW    (K_DIM / 2)       // packed int32 per weight row

#define BM 128
#define BN 256
#define BK 64                   // K-elems per tile iteration
#define K_ITERS (K_DIM / BK)    // 64
#define THREADS 256

// smem: A double 2x16KB, B double 2x32KB = 96KB
#define SM_A(s)   ((s) * (BM * 128))
#define SM_B(s)   (2 * BM * 128 + (s) * (BN * 128))
#define SMEM_BYTES (2 * BM * 128 + 2 * BN * 128)

#define SWZ(off) ((off) ^ (((off) >> 3) & 0x70))

// ---------------- device scratch (16 + 45 MB — R5-proven footprint) --------
__device__ uint8_t g_qx[(size_t)M_DIM * K_DIM];    // biased activations: qi + 128
__device__ uint8_t g_wb[(size_t)N_DIM * K_DIM];    // biased weights: (w - z) + 128

__device__ __forceinline__ uint32_t smem_u32(const void* p) {
    uint32_t a;
    asm("{ .reg .u64 t; cvta.to.shared.u64 t, %1; cvt.u32.u64 %0, t; }" : "=r"(a) : "l"(p));
    return a;
}
__device__ __forceinline__ uint32_t hsub2(uint32_t a, uint32_t b) {
    uint32_t r;
    asm("sub.rn.f16x2 %0, %1, %2;" : "=r"(r) : "r"(a), "r"(b));
    return r;
}
// 16 biased u8 (int4) -> 8 fp16x2 words, value - 1152
__device__ __forceinline__ void cvt16(const int4 w, uint32_t o[8]) {
    const uint32_t v[4] = {(uint32_t)w.x, (uint32_t)w.y, (uint32_t)w.z, (uint32_t)w.w};
#pragma unroll
    for (int t = 0; t < 4; t++) {
        uint32_t w01 = __byte_perm(v[t], 0u, 0x4140) | 0x64006400u;
        uint32_t w23 = __byte_perm(v[t], 0u, 0x4342) | 0x64006400u;
        o[2*t]   = hsub2(w01, 0x64806480u);   // fp16(1152) pair
        o[2*t+1] = hsub2(w23, 0x64806480u);
    }
}

// ---------------- kernel 1: static fake-quant x -> biased u8 ---------------
__global__ void quant_kernel(const float* __restrict__ x,
                             const float* __restrict__ clampv) {
    const float cv  = clampv[0];
    const float inv = 127.0f / cv;
    size_t i = (size_t)blockIdx.x * blockDim.x + threadIdx.x;   // over M*K/4
    float4 v = reinterpret_cast<const float4*>(x)[i];
    uint32_t a = (uint32_t)(max(-127, min(127, __float2int_rn(fminf(fmaxf(v.x, -cv), cv) * inv))) + 128);
    uint32_t b = (uint32_t)(max(-127, min(127, __float2int_rn(fminf(fmaxf(v.y, -cv), cv) * inv))) + 128);
    uint32_t c = (uint32_t)(max(-127, min(127, __float2int_rn(fminf(fmaxf(v.z, -cv), cv) * inv))) + 128);
    uint32_t d = (uint32_t)(max(-127, min(127, __float2int_rn(fminf(fmaxf(v.w, -cv), cv) * inv))) + 128);
    reinterpret_cast<uint32_t*>(g_qx)[i] = a | (b << 8) | (c << 16) | (d << 24);
}

// ---------------- kernel 2: unpack int4 -> biased u8 (w - z + 128) ---------
// qweight int32 holds ONE byte: hi nibble -> even k, lo nibble -> odd k.
__global__ void unpackb_kernel(const int* __restrict__ qw, const int* __restrict__ qz) {
    size_t idx = (size_t)blockIdx.x * blockDim.x + threadIdx.x;  // over N*KW/4
    const int n = (int)(idx >> 9);                               // 512 threads per row
    const int zb = 128 - qz[n];
    int4 q = reinterpret_cast<const int4*>(qw)[idx];
    const int v[4] = {q.x, q.y, q.z, q.w};
    uint32_t lo = 0, hi = 0;
#pragma unroll
    for (int t = 0; t < 2; t++) {
        uint32_t e0 = (uint32_t)(((v[t] >> 4) & 15) + zb);
        uint32_t e1 = (uint32_t)((v[t] & 15) + zb);
        lo |= (e0 | (e1 << 8)) << (t * 16);
        uint32_t f0 = (uint32_t)(((v[t+2] >> 4) & 15) + zb);
        uint32_t f1 = (uint32_t)((v[t+2] & 15) + zb);
        hi |= (f0 | (f1 << 8)) << (t * 16);
    }
    reinterpret_cast<uint2*>(g_wb)[idx] = make_uint2(lo, hi);
}

// ---------------- kernel 3: fused fp16 GEMM, 64x64 warp tiles --------------
__global__ __launch_bounds__(THREADS, 1)
void gemm_kernel(const float* __restrict__ sc,
                 const float* __restrict__ bias,
                 const float* __restrict__ clampv,
                 float* __restrict__ C) {
    extern __shared__ char smem[];
    const uint32_t sbase = smem_u32(smem);
    const int tid  = threadIdx.x;
    const int wid  = tid >> 5;
    const int lane = tid & 31;
    const int m0 = blockIdx.y * BM;
    const int n0 = blockIdx.x * BN;
    const int warp_m = (wid & 1) * 64;    // 2 warp-rows
    const int warp_n = (wid >> 1) * 64;   // 4 warp-cols

    float acc[4][8][4];
#pragma unroll
    for (int f = 0; f < 4; f++)
#pragma unroll
        for (int j = 0; j < 8; j++)
#pragma unroll
            for (int q = 0; q < 4; q++) acc[f][j][q] = 0.0f;

    // A geometry: u8 tile 128 x 64B = 512 x 16B chunks, 2/thread
    const int a_row = tid >> 2;          // 0..63 (+64 for 2nd chunk)
    const int a_seg = tid & 3;
    const uint8_t* gA0 = g_qx + (size_t)(m0 + a_row)      * K_DIM + a_seg * 16;
    const uint8_t* gA1 = g_qx + (size_t)(m0 + a_row + 64) * K_DIM + a_seg * 16;

    // B geometry: one row per thread, 64 u8 = 4 x int4 per iter
    const int b_row = tid;
    const uint8_t* gB = g_wb + (size_t)(n0 + b_row) * K_DIM;

    // prefetch iter 0
    int4 awreg[2], bwreg[4];
    awreg[0] = *reinterpret_cast<const int4*>(gA0);
    awreg[1] = *reinterpret_cast<const int4*>(gA1);
#pragma unroll
    for (int q = 0; q < 4; q++)
        bwreg[q] = reinterpret_cast<const int4*>(gB)[q];

#pragma unroll 1
    for (int it = 0; it < K_ITERS; it++) {
        const int s = it & 1;
        char* smA = smem + SM_A(s);
        char* smB = smem + SM_B(s);

        // ---- A convert ----
#pragma unroll
        for (int h = 0; h < 2; h++) {
            uint32_t o[8];
            cvt16(awreg[h], o);
            uint32_t off = (uint32_t)((a_row + h * 64) * 128 + a_seg * 32);
            *reinterpret_cast<uint4*>(smA + SWZ(off))      = *reinterpret_cast<uint4*>(&o[0]);
            *reinterpret_cast<uint4*>(smA + SWZ(off + 16)) = *reinterpret_cast<uint4*>(&o[4]);
        }
        // ---- B convert: 64 u8 of one row -> 128B fp16 ----
#pragma unroll
        for (int cch = 0; cch < 4; cch++) {
            uint32_t o[8];
            cvt16(bwreg[cch], o);
            uint32_t off = (uint32_t)(b_row * 128 + cch * 32);
            *reinterpret_cast<uint4*>(smB + SWZ(off))      = *reinterpret_cast<uint4*>(&o[0]);
            *reinterpret_cast<uint4*>(smB + SWZ(off + 16)) = *reinterpret_cast<uint4*>(&o[4]);
        }

        // ---- prefetch next iter ----
        if (it + 1 < K_ITERS) {
            const int knext = (it + 1) * BK;
            awreg[0] = *reinterpret_cast<const int4*>(gA0 + knext);
            awreg[1] = *reinterpret_cast<const int4*>(gA1 + knext);
            const uint8_t* gBn = gB + knext;
#pragma unroll
            for (int q = 0; q < 4; q++)
                bwreg[q] = reinterpret_cast<const int4*>(gBn)[q];
        }

        __syncthreads();

        const uint32_t sA = sbase + SM_A(s);
        const uint32_t sB = sbase + SM_B(s);

#pragma unroll
        for (int ks = 0; ks < 4; ks++) {
            uint32_t a[4][4];
#pragma unroll
            for (int f = 0; f < 4; f++) {
                uint32_t off = (uint32_t)((warp_m + f * 16 + (lane & 15)) * 128
                                          + ks * 32 + (lane >> 4) * 16);
                asm volatile("ldmatrix.sync.aligned.m8n8.x4.shared.b16 {%0,%1,%2,%3}, [%4];"
                             : "=r"(a[f][0]), "=r"(a[f][1]), "=r"(a[f][2]), "=r"(a[f][3])
                             : "r"(sA + SWZ(off)));
            }
            uint32_t b[4][4];
#pragma unroll
            for (int p = 0; p < 4; p++) {
                uint32_t off = (uint32_t)((warp_n + p * 16 + (lane & 15)) * 128
                                          + ks * 32 + (lane >> 4) * 16);
                asm volatile("ldmatrix.sync.aligned.m8n8.x4.shared.b16 {%0,%1,%2,%3}, [%4];"
                             : "=r"(b[p][0]), "=r"(b[p][1]), "=r"(b[p][2]), "=r"(b[p][3])
                             : "r"(sB + SWZ(off)));
            }
#pragma unroll
            for (int f = 0; f < 4; f++)
#pragma unroll
                for (int j = 0; j < 8; j++) {
                    asm volatile(
                        "mma.sync.aligned.m16n8k16.row.col.f32.f16.f16.f32 "
                        "{%0,%1,%2,%3}, {%4,%5,%6,%7}, {%8,%9}, {%0,%1,%2,%3};"
                        : "+f"(acc[f][j][0]), "+f"(acc[f][j][1]),
                          "+f"(acc[f][j][2]), "+f"(acc[f][j][3])
                        : "r"(a[f][0]), "r"(a[f][1]), "r"(a[f][2]), "r"(a[f][3]),
                          "r"(b[j >> 1][j & 1]), "r"(b[j >> 1][(j & 1) + 2]));
                }
        }
    }

    // ---- epilogue: out = ascale*scale[n]*acc + bias[n] ----
    const float ascale = clampv[0] * (1.0f / 127.0f);
#pragma unroll
    for (int f = 0; f < 4; f++) {
        int r0 = m0 + warp_m + f * 16 + (lane >> 2);
#pragma unroll
        for (int j = 0; j < 8; j++) {
            int col = n0 + warp_n + j * 8 + (lane & 3) * 2;
            float2 s2 = *reinterpret_cast<const float2*>(sc + col);
            float2 b2 = *reinterpret_cast<const float2*>(bias + col);
            float s0 = ascale * s2.x, s1 = ascale * s2.y;
            float2 o0, o1;
            o0.x = s0 * acc[f][j][0] + b2.x;
            o0.y = s1 * acc[f][j][1] + b2.y;
            o1.x = s0 * acc[f][j][2] + b2.x;
            o1.y = s1 * acc[f][j][3] + b2.y;
            *reinterpret_cast<float2*>(C + (size_t)r0 * N_DIM + col) = o0;
            *reinterpret_cast<float2*>(C + (size_t)(r0 + 8) * N_DIM + col) = o1;
        }
    }
}

// ---------------- launch ---------------------------------------------------
extern "C" void kernel_launch(void* const* d_in, const int* in_sizes, int n_in,
                              void* d_out, int out_size) {
    const float* x      = (const float*)d_in[0];
    const int*   qw     = (const int*)d_in[1];
    const int*   qz     = (const int*)d_in[2];
    const float* sc     = (const float*)d_in[3];
    const float* bias   = (const float*)d_in[4];
    const float* clampv = (const float*)d_in[5];
    float* out = (float*)d_out;

    cudaFuncSetAttribute(gemm_kernel, cudaFuncAttributeMaxDynamicSharedMemorySize, SMEM_BYTES);

    quant_kernel<<<(M_DIM * (K_DIM / 4)) / 256, 256>>>(x, clampv);

    const size_t nb = (size_t)N_DIM * KW / 4;   // threads for unpack
    unpackb_kernel<<<(unsigned)(nb / 256), 256>>>(qw, qz);

    dim3 grid(N_DIM / BN, M_DIM / BM);
    gemm_kernel<<<grid, THREADS, SMEM_BYTES>>>(sc, bias, clampv, out);
}